// round 14
// baseline (speedup 1.0000x reference)
#include <cuda_runtime.h>
#include <math.h>

#define Hf 128
#define Wf 128
#define HH 512
#define WH 512
#define C  64
#define NQ (HH*WH)

// ---- device scratch (static allocation only; no cudaMalloc allowed) ----
__device__ float g_feat[Hf*Wf*C];       // [y][x][c]   4 MB
__device__ float g_body[(size_t)HH*WH*C]; // [y][x][c]  64 MB  (out2 + fea0)
__device__ float g_pred[(size_t)HH*WH*3]; // [y][x][o]   3 MB
__device__ float g_Wc[16*8*C];          // [ph][k][c]  effective compress
__device__ float g_We[16*C*8];          // [ph][c][k]  effective expand
__device__ float g_off[16*2];           // [ph][{x,y}]

// ======================================================================
// Kernel 1: encoder conv 3x3, 3->64, pad 1, output channel-last
// ======================================================================
__global__ __launch_bounds__(256) void enc_kernel(
    const float* __restrict__ inp, const float* __restrict__ ew,
    const float* __restrict__ eb)
{
    __shared__ float sw[64*27];
    __shared__ float sb[64];
    int tid = threadIdx.y*16 + threadIdx.x;
    for (int i = tid; i < 64*27; i += 256) sw[i] = ew[i];
    if (tid < 64) sb[tid] = eb[tid];
    __syncthreads();

    int x = blockIdx.x*16 + threadIdx.x;
    int y = blockIdx.y*16 + threadIdx.y;

    float v[27];
#pragma unroll
    for (int ci = 0; ci < 3; ci++)
#pragma unroll
        for (int ky = 0; ky < 3; ky++)
#pragma unroll
            for (int kx = 0; kx < 3; kx++) {
                int yy = y + ky - 1, xx = x + kx - 1;
                float t = 0.f;
                if ((unsigned)yy < (unsigned)Hf && (unsigned)xx < (unsigned)Wf)
                    t = inp[ci*(Hf*Wf) + yy*Wf + xx];
                v[ci*9 + ky*3 + kx] = t;
            }

    float* outp = g_feat + ((size_t)y*Wf + x)*C;
#pragma unroll 4
    for (int o = 0; o < 64; o++) {
        float acc = sb[o];
        const float* wp = sw + o*27;
#pragma unroll
        for (int j = 0; j < 27; j++) acc += v[j]*wp[j];
        outp[o] = acc;
    }
}

// ======================================================================
// Kernel 2: the entire MLP collapses to 16 phases (y%4, x%4).
// Computes per-phase offset, routing, and effective 8x64 / 64x8 matrices.
// One block of (64, 16) threads: thread (c, ph).
// ======================================================================
__global__ void phase_kernel(
    const float* __restrict__ w1, const float* __restrict__ b1,
    const float* __restrict__ w2, const float* __restrict__ b2,
    const float* __restrict__ rw, const float* __restrict__ rb,
    const float* __restrict__ ow, const float* __restrict__ ob,
    const float* __restrict__ wc, const float* __restrict__ we)
{
    __shared__ float semb1[16][64];
    __shared__ float semb2[16][64];
    __shared__ float sr[16][4];

    int c  = threadIdx.x;   // 0..63
    int ph = threadIdx.y;   // 0..15 : ph = (y&3)*4 + (x&3)

    float chh = -0.375f + 0.25f*(float)(ph >> 2);  // coor_h(y%4)
    float cww = -0.375f + 0.25f*(float)(ph & 3);   // coor_w(x%4)

    // emb1 = relu(W1 @ [0.25, 0.25, ch, cw] + b1)
    float a = b1[c] + 0.25f*w1[c*4+0] + 0.25f*w1[c*4+1]
            + chh*w1[c*4+2] + cww*w1[c*4+3];
    semb1[ph][c] = fmaxf(a, 0.f);
    __syncthreads();

    // emb2 = relu(W2 @ emb1 + b2)
    float acc = b2[c];
#pragma unroll 8
    for (int j = 0; j < 64; j++) acc += w2[c*64 + j]*semb1[ph][j];
    semb2[ph][c] = fmaxf(acc, 0.f);
    __syncthreads();

    if (c < 4) {
        float s = rb[c];
        for (int j = 0; j < 64; j++) s += rw[c*64 + j]*semb2[ph][j];
        sr[ph][c] = 1.f/(1.f + expf(-s));
    } else if (c < 6) {
        int o = c - 4;
        float s = ob[o];
        for (int j = 0; j < 64; j++) s += ow[o*64 + j]*semb2[ph][j];
        g_off[ph*2 + o] = s;   // o=0 -> x offset, o=1 -> y offset
    }
    __syncthreads();

    float r0 = sr[ph][0], r1 = sr[ph][1], r2 = sr[ph][2], r3 = sr[ph][3];
    // Wc_eff[ph][k][c] = sum_e r_e * wc[e][k][c]   (wc: [E][8][64])
    // We_eff[ph][c][k] = sum_e r_e * we[e][c][k]   (we: [E][64][8])
#pragma unroll
    for (int k = 0; k < 8; k++) {
        g_Wc[ph*512 + k*64 + c] =
            r0*wc[0*512 + k*64 + c] + r1*wc[1*512 + k*64 + c] +
            r2*wc[2*512 + k*64 + c] + r3*wc[3*512 + k*64 + c];
        g_We[ph*512 + c*8 + k] =
            r0*we[0*512 + c*8 + k] + r1*we[1*512 + c*8 + k] +
            r2*we[2*512 + c*8 + k] + r3*we[3*512 + c*8 + k];
    }
}

// ======================================================================
// Kernel 3: main pixel kernel. Phase-uniform blocks (all 256 threads in a
// block share one phase -> weight reads are smem broadcasts).
// Per pixel: bilinear-gather 64-ch fea0, 64->8->64 bottleneck, write
// body = out2 + fea0 (channel-last).
// ======================================================================
__global__ __launch_bounds__(256) void main_kernel()
{
    __shared__ float sWc[512];
    __shared__ float sWe[512];
    __shared__ float soff[2];

    int ph  = blockIdx.z;
    int tid = threadIdx.y*16 + threadIdx.x;
    for (int i = tid; i < 512; i += 256) {
        sWc[i] = g_Wc[ph*512 + i];
        sWe[i] = g_We[ph*512 + i];
    }
    if (tid < 2) soff[tid] = g_off[ph*2 + tid];
    __syncthreads();

    int x = blockIdx.x*64 + threadIdx.x*4 + (ph & 3);
    int y = blockIdx.y*64 + threadIdx.y*4 + (ph >> 2);

    // feat-space sampling coords:  (gx+1)*0.5*(W-1) == (x+0.5)/4 - 0.5 + off
    float px = ((float)x + 0.5f)*0.25f - 0.5f + soff[0];
    float py = ((float)y + 0.5f)*0.25f - 0.5f + soff[1];

    float x0f = floorf(px), y0f = floorf(py);
    float fx = px - x0f, fy = py - y0f;
    int x0 = (int)x0f, y0 = (int)y0f;
    int x1 = x0 + 1,   y1 = y0 + 1;

    float w00 = (1.f-fy)*(1.f-fx), w01 = (1.f-fy)*fx;
    float w10 = fy*(1.f-fx),       w11 = fy*fx;

    bool vx0 = (unsigned)x0 < 128u, vx1 = (unsigned)x1 < 128u;
    bool vy0 = (unsigned)y0 < 128u, vy1 = (unsigned)y1 < 128u;
    if (!(vy0 && vx0)) w00 = 0.f;
    if (!(vy0 && vx1)) w01 = 0.f;
    if (!(vy1 && vx0)) w10 = 0.f;
    if (!(vy1 && vx1)) w11 = 0.f;

    int x0c = min(max(x0,0),127), x1c = min(max(x1,0),127);
    int y0c = min(max(y0,0),127), y1c = min(max(y1,0),127);

    const float4* p00 = (const float4*)(g_feat + ((size_t)y0c*Wf + x0c)*C);
    const float4* p01 = (const float4*)(g_feat + ((size_t)y0c*Wf + x1c)*C);
    const float4* p10 = (const float4*)(g_feat + ((size_t)y1c*Wf + x0c)*C);
    const float4* p11 = (const float4*)(g_feat + ((size_t)y1c*Wf + x1c)*C);

    float fea[64];
#pragma unroll
    for (int i = 0; i < 16; i++) {
        float4 a = p00[i], b = p01[i], cc = p10[i], d = p11[i];
        fea[4*i+0] = w00*a.x + w01*b.x + w10*cc.x + w11*d.x;
        fea[4*i+1] = w00*a.y + w01*b.y + w10*cc.y + w11*d.y;
        fea[4*i+2] = w00*a.z + w01*b.z + w10*cc.z + w11*d.z;
        fea[4*i+3] = w00*a.w + w01*b.w + w10*cc.w + w11*d.w;
    }

    // mid = Wc_eff @ fea0   (8x64)
    float mid[8];
    const float4* wc4 = (const float4*)sWc;
#pragma unroll
    for (int k = 0; k < 8; k++) {
        float m = 0.f;
#pragma unroll
        for (int i = 0; i < 16; i++) {
            float4 w = wc4[k*16 + i];
            m += fea[4*i+0]*w.x + fea[4*i+1]*w.y + fea[4*i+2]*w.z + fea[4*i+3]*w.w;
        }
        mid[k] = m;
    }

    // body = We_eff @ mid + fea0
    const float4* we4 = (const float4*)sWe;
    float4* outp = (float4*)(g_body + ((size_t)y*WH + x)*C);
#pragma unroll
    for (int i = 0; i < 16; i++) {
        float4 o;
        float* op = &o.x;
#pragma unroll
        for (int j = 0; j < 4; j++) {
            int c = 4*i + j;
            float4 wa = we4[c*2], wb = we4[c*2 + 1];
            op[j] = fea[c]
                  + wa.x*mid[0] + wa.y*mid[1] + wa.z*mid[2] + wa.w*mid[3]
                  + wb.x*mid[4] + wb.y*mid[5] + wb.z*mid[6] + wb.w*mid[7];
        }
        outp[i] = o;
    }
}

// ======================================================================
// Kernel 4: tail conv 3x3, 64->3, pad 1. body is L2-resident (64MB < 126MB).
// ======================================================================
__global__ __launch_bounds__(256) void tail_kernel(
    const float* __restrict__ tw, const float* __restrict__ tb)
{
    __shared__ float sw[3*576];   // [o][ky*3+kx][c]
    int tid = threadIdx.y*16 + threadIdx.x;
    for (int idx = tid; idx < 1728; idx += 256) {
        int o = idx/576, rem = idx%576, p = rem/64, c = rem%64;
        sw[idx] = tw[o*576 + c*9 + p];
    }
    __syncthreads();

    int x = blockIdx.x*16 + threadIdx.x;
    int y = blockIdx.y*16 + threadIdx.y;

    float a0 = tb[0], a1 = tb[1], a2 = tb[2];
#pragma unroll
    for (int ky = 0; ky < 3; ky++) {
        int yy = y + ky - 1;
        if ((unsigned)yy >= (unsigned)HH) continue;
#pragma unroll
        for (int kx = 0; kx < 3; kx++) {
            int xx = x + kx - 1;
            if ((unsigned)xx >= (unsigned)WH) continue;
            const float4* bp = (const float4*)(g_body + ((size_t)yy*WH + xx)*C);
            int p = ky*3 + kx;
            const float4* q0 = (const float4*)(sw + p*64);
            const float4* q1 = (const float4*)(sw + 576 + p*64);
            const float4* q2 = (const float4*)(sw + 1152 + p*64);
#pragma unroll
            for (int i = 0; i < 16; i++) {
                float4 v  = bp[i];
                float4 u0 = q0[i], u1 = q1[i], u2 = q2[i];
                a0 += v.x*u0.x + v.y*u0.y + v.z*u0.z + v.w*u0.w;
                a1 += v.x*u1.x + v.y*u1.y + v.z*u1.z + v.w*u1.w;
                a2 += v.x*u2.x + v.y*u2.y + v.z*u2.z + v.w*u2.w;
            }
        }
    }
    float* pp = g_pred + ((size_t)y*WH + x)*3;
    pp[0] = a0; pp[1] = a1; pp[2] = a2;
}

// ======================================================================
// Kernel 5: nearest-neighbor query gather (round-half-even like jnp.round)
// ======================================================================
__global__ void query_kernel(const float* __restrict__ coord,
                             const float* __restrict__ cell,
                             float* __restrict__ out)
{
    int q = blockIdx.x*256 + threadIdx.x;
    if (q >= NQ) return;
    float gy = coord[2*q+0] - cell[2*q+0]*0.5f + 1e-6f;
    float gx = coord[2*q+1] - cell[2*q+1]*0.5f + 1e-6f;
    gy = fminf(fmaxf(gy, -1.f + 1e-6f), 1.f - 1e-6f);
    gx = fminf(fmaxf(gx, -1.f + 1e-6f), 1.f - 1e-6f);
    int xi = (int)rintf((gx + 1.f)*0.5f*511.f);
    int yi = (int)rintf((gy + 1.f)*0.5f*511.f);
    xi = min(max(xi, 0), 511);
    yi = min(max(yi, 0), 511);
    const float* pp = g_pred + ((size_t)yi*WH + xi)*3;
    out[3*q+0] = pp[0];
    out[3*q+1] = pp[1];
    out[3*q+2] = pp[2];
}

// ======================================================================
extern "C" void kernel_launch(void* const* d_in, const int* in_sizes, int n_in,
                              void* d_out, int out_size)
{
    const float* inp   = (const float*)d_in[0];
    const float* coord = (const float*)d_in[1];
    const float* cell  = (const float*)d_in[2];
    const float* enc_w = (const float*)d_in[3];
    const float* enc_b = (const float*)d_in[4];
    const float* w1    = (const float*)d_in[5];
    const float* b1    = (const float*)d_in[6];
    const float* w2    = (const float*)d_in[7];
    const float* b2    = (const float*)d_in[8];
    const float* rw    = (const float*)d_in[9];
    const float* rb    = (const float*)d_in[10];
    const float* ow    = (const float*)d_in[11];
    const float* ob    = (const float*)d_in[12];
    const float* tw    = (const float*)d_in[13];
    const float* tb    = (const float*)d_in[14];
    const float* wc    = (const float*)d_in[15];
    const float* we    = (const float*)d_in[16];
    float* out = (float*)d_out;

    enc_kernel<<<dim3(8,8), dim3(16,16)>>>(inp, enc_w, enc_b);
    phase_kernel<<<1, dim3(64,16)>>>(w1,b1,w2,b2,rw,rb,ow,ob,wc,we);
    main_kernel<<<dim3(8,8,16), dim3(16,16)>>>();
    tail_kernel<<<dim3(32,32), dim3(16,16)>>>(tw, tb);
    query_kernel<<<NQ/256, 256>>>(coord, cell, out);
}

// round 15
// speedup vs baseline: 2.0637x; 2.0637x over previous
#include <cuda_runtime.h>
#include <math.h>

#define Hf 128
#define Wf 128
#define HH 512
#define WH 512
#define C  64
#define NQ (HH*WH)

// ---- device scratch (static allocation only) ----
// Plane-of-float4 layout: plane i holds channels [4i, 4i+4)
__device__ float4 g_feat[16*Hf*Wf];            //  4 MB
__device__ float4 g_body[(size_t)16*HH*WH];    // 64 MB
__device__ float  g_pred[(size_t)HH*WH*3];     //  3 MB
__device__ float  g_Wc[16*8*C];                // [ph][k][c]
__device__ float  g_We[16*C*8];                // [ph][c][k]
__device__ float  g_off[16*2];                 // [ph][{x,y}]

// ======================================================================
// Kernel 1: encoder conv 3x3, 3->64, pad 1 -> plane layout
// ======================================================================
__global__ __launch_bounds__(256) void enc_kernel(
    const float* __restrict__ inp, const float* __restrict__ ew,
    const float* __restrict__ eb)
{
    __shared__ float sw[64*27];
    __shared__ float sb[64];
    int tid = threadIdx.y*16 + threadIdx.x;
    for (int i = tid; i < 64*27; i += 256) sw[i] = ew[i];
    if (tid < 64) sb[tid] = eb[tid];
    __syncthreads();

    int x = blockIdx.x*16 + threadIdx.x;
    int y = blockIdx.y*16 + threadIdx.y;

    float v[27];
#pragma unroll
    for (int ci = 0; ci < 3; ci++)
#pragma unroll
        for (int ky = 0; ky < 3; ky++)
#pragma unroll
            for (int kx = 0; kx < 3; kx++) {
                int yy = y + ky - 1, xx = x + kx - 1;
                float t = 0.f;
                if ((unsigned)yy < (unsigned)Hf && (unsigned)xx < (unsigned)Wf)
                    t = inp[ci*(Hf*Wf) + yy*Wf + xx];
                v[ci*9 + ky*3 + kx] = t;
            }

    int pix = y*Wf + x;
#pragma unroll
    for (int i = 0; i < 16; i++) {
        float o4[4];
#pragma unroll
        for (int j = 0; j < 4; j++) {
            int o = 4*i + j;
            float acc = sb[o];
            const float* wp = sw + o*27;
#pragma unroll
            for (int t = 0; t < 27; t++) acc += v[t]*wp[t];
            o4[j] = acc;
        }
        g_feat[i*(Hf*Wf) + pix] = make_float4(o4[0], o4[1], o4[2], o4[3]);
    }
}

// ======================================================================
// Kernel 2: 16-phase MLP collapse (unchanged)
// ======================================================================
__global__ void phase_kernel(
    const float* __restrict__ w1, const float* __restrict__ b1,
    const float* __restrict__ w2, const float* __restrict__ b2,
    const float* __restrict__ rw, const float* __restrict__ rb,
    const float* __restrict__ ow, const float* __restrict__ ob,
    const float* __restrict__ wc, const float* __restrict__ we)
{
    __shared__ float semb1[16][64];
    __shared__ float semb2[16][64];
    __shared__ float sr[16][4];

    int c  = threadIdx.x;   // 0..63
    int ph = threadIdx.y;   // 0..15 : ph = (y&3)*4 + (x&3)

    float chh = -0.375f + 0.25f*(float)(ph >> 2);
    float cww = -0.375f + 0.25f*(float)(ph & 3);

    float a = b1[c] + 0.25f*w1[c*4+0] + 0.25f*w1[c*4+1]
            + chh*w1[c*4+2] + cww*w1[c*4+3];
    semb1[ph][c] = fmaxf(a, 0.f);
    __syncthreads();

    float acc = b2[c];
#pragma unroll 8
    for (int j = 0; j < 64; j++) acc += w2[c*64 + j]*semb1[ph][j];
    semb2[ph][c] = fmaxf(acc, 0.f);
    __syncthreads();

    if (c < 4) {
        float s = rb[c];
        for (int j = 0; j < 64; j++) s += rw[c*64 + j]*semb2[ph][j];
        sr[ph][c] = 1.f/(1.f + expf(-s));
    } else if (c < 6) {
        int o = c - 4;
        float s = ob[o];
        for (int j = 0; j < 64; j++) s += ow[o*64 + j]*semb2[ph][j];
        g_off[ph*2 + o] = s;
    }
    __syncthreads();

    float r0 = sr[ph][0], r1 = sr[ph][1], r2 = sr[ph][2], r3 = sr[ph][3];
#pragma unroll
    for (int k = 0; k < 8; k++) {
        g_Wc[ph*512 + k*64 + c] =
            r0*wc[0*512 + k*64 + c] + r1*wc[1*512 + k*64 + c] +
            r2*wc[2*512 + k*64 + c] + r3*wc[3*512 + k*64 + c];
        g_We[ph*512 + c*8 + k] =
            r0*we[0*512 + c*8 + k] + r1*we[1*512 + c*8 + k] +
            r2*we[2*512 + c*8 + k] + r3*we[3*512 + c*8 + k];
    }
}

// ======================================================================
// Kernel 3: main pixel kernel (phase-uniform blocks, plane layout)
// ======================================================================
__global__ __launch_bounds__(256) void main_kernel()
{
    __shared__ float sWc[512];
    __shared__ float sWe[512];
    __shared__ float soff[2];

    int ph  = blockIdx.z;
    int tid = threadIdx.y*16 + threadIdx.x;
    for (int i = tid; i < 512; i += 256) {
        sWc[i] = g_Wc[ph*512 + i];
        sWe[i] = g_We[ph*512 + i];
    }
    if (tid < 2) soff[tid] = g_off[ph*2 + tid];
    __syncthreads();

    int x = blockIdx.x*64 + threadIdx.x*4 + (ph & 3);
    int y = blockIdx.y*64 + threadIdx.y*4 + (ph >> 2);

    float px = ((float)x + 0.5f)*0.25f - 0.5f + soff[0];
    float py = ((float)y + 0.5f)*0.25f - 0.5f + soff[1];

    float x0f = floorf(px), y0f = floorf(py);
    float fx = px - x0f, fy = py - y0f;
    int x0 = (int)x0f, y0 = (int)y0f;
    int x1 = x0 + 1,   y1 = y0 + 1;

    float w00 = (1.f-fy)*(1.f-fx), w01 = (1.f-fy)*fx;
    float w10 = fy*(1.f-fx),       w11 = fy*fx;

    bool vx0 = (unsigned)x0 < 128u, vx1 = (unsigned)x1 < 128u;
    bool vy0 = (unsigned)y0 < 128u, vy1 = (unsigned)y1 < 128u;
    if (!(vy0 && vx0)) w00 = 0.f;
    if (!(vy0 && vx1)) w01 = 0.f;
    if (!(vy1 && vx0)) w10 = 0.f;
    if (!(vy1 && vx1)) w11 = 0.f;

    int x0c = min(max(x0,0),127), x1c = min(max(x1,0),127);
    int y0c = min(max(y0,0),127), y1c = min(max(y1,0),127);

    int i00 = y0c*Wf + x0c, i01 = y0c*Wf + x1c;
    int i10 = y1c*Wf + x0c, i11 = y1c*Wf + x1c;

    float fea[64];
#pragma unroll
    for (int i = 0; i < 16; i++) {
        const float4* pl = g_feat + i*(Hf*Wf);
        float4 a = pl[i00], b = pl[i01], cc = pl[i10], d = pl[i11];
        fea[4*i+0] = w00*a.x + w01*b.x + w10*cc.x + w11*d.x;
        fea[4*i+1] = w00*a.y + w01*b.y + w10*cc.y + w11*d.y;
        fea[4*i+2] = w00*a.z + w01*b.z + w10*cc.z + w11*d.z;
        fea[4*i+3] = w00*a.w + w01*b.w + w10*cc.w + w11*d.w;
    }

    // mid = Wc_eff @ fea0   (8x64)
    float mid[8];
    const float4* wc4 = (const float4*)sWc;
#pragma unroll
    for (int k = 0; k < 8; k++) {
        float m = 0.f;
#pragma unroll
        for (int i = 0; i < 16; i++) {
            float4 w = wc4[k*16 + i];
            m += fea[4*i+0]*w.x + fea[4*i+1]*w.y + fea[4*i+2]*w.z + fea[4*i+3]*w.w;
        }
        mid[k] = m;
    }

    // body = We_eff @ mid + fea0  -> plane layout
    const float4* we4 = (const float4*)sWe;
    size_t pix = (size_t)y*WH + x;
#pragma unroll
    for (int i = 0; i < 16; i++) {
        float4 o;
        float* op = &o.x;
#pragma unroll
        for (int j = 0; j < 4; j++) {
            int c = 4*i + j;
            float4 wa = we4[c*2], wb = we4[c*2 + 1];
            op[j] = fea[c]
                  + wa.x*mid[0] + wa.y*mid[1] + wa.z*mid[2] + wa.w*mid[3]
                  + wb.x*mid[4] + wb.y*mid[5] + wb.z*mid[6] + wb.w*mid[7];
        }
        g_body[(size_t)i*(HH*WH) + pix] = o;
    }
}

// ======================================================================
// Kernel 4: tail conv 3x3, 64->3, pad 1, plane layout, coalesced reads.
// Block = 32x8 so each warp is one contiguous row of 32 pixels.
// ======================================================================
__global__ __launch_bounds__(256) void tail_kernel(
    const float* __restrict__ tw, const float* __restrict__ tb)
{
    __shared__ float sw[3*576];   // [o][ky*3+kx][c]
    int tid = threadIdx.y*32 + threadIdx.x;
    for (int idx = tid; idx < 1728; idx += 256) {
        int o = idx/576, rem = idx%576, p = rem/64, c = rem%64;
        sw[idx] = tw[o*576 + c*9 + p];
    }
    __syncthreads();

    int x = blockIdx.x*32 + threadIdx.x;
    int y = blockIdx.y*8  + threadIdx.y;

    float a0 = tb[0], a1 = tb[1], a2 = tb[2];
#pragma unroll
    for (int ky = 0; ky < 3; ky++) {
        int yy = y + ky - 1;
        if ((unsigned)yy >= (unsigned)HH) continue;
#pragma unroll
        for (int kx = 0; kx < 3; kx++) {
            int xx = x + kx - 1;
            if ((unsigned)xx >= (unsigned)WH) continue;
            size_t pix = (size_t)yy*WH + xx;
            int p = ky*3 + kx;
            const float4* q0 = (const float4*)(sw + p*64);
            const float4* q1 = (const float4*)(sw + 576 + p*64);
            const float4* q2 = (const float4*)(sw + 1152 + p*64);
#pragma unroll
            for (int i = 0; i < 16; i++) {
                float4 v  = g_body[(size_t)i*(HH*WH) + pix];
                float4 u0 = q0[i], u1 = q1[i], u2 = q2[i];
                a0 += v.x*u0.x + v.y*u0.y + v.z*u0.z + v.w*u0.w;
                a1 += v.x*u1.x + v.y*u1.y + v.z*u1.z + v.w*u1.w;
                a2 += v.x*u2.x + v.y*u2.y + v.z*u2.z + v.w*u2.w;
            }
        }
    }
    float* pp = g_pred + ((size_t)y*WH + x)*3;
    pp[0] = a0; pp[1] = a1; pp[2] = a2;
}

// ======================================================================
// Kernel 5: nearest-neighbor query gather
// ======================================================================
__global__ void query_kernel(const float* __restrict__ coord,
                             const float* __restrict__ cell,
                             float* __restrict__ out)
{
    int q = blockIdx.x*256 + threadIdx.x;
    if (q >= NQ) return;
    float gy = coord[2*q+0] - cell[2*q+0]*0.5f + 1e-6f;
    float gx = coord[2*q+1] - cell[2*q+1]*0.5f + 1e-6f;
    gy = fminf(fmaxf(gy, -1.f + 1e-6f), 1.f - 1e-6f);
    gx = fminf(fmaxf(gx, -1.f + 1e-6f), 1.f - 1e-6f);
    int xi = (int)rintf((gx + 1.f)*0.5f*511.f);
    int yi = (int)rintf((gy + 1.f)*0.5f*511.f);
    xi = min(max(xi, 0), 511);
    yi = min(max(yi, 0), 511);
    const float* pp = g_pred + ((size_t)yi*WH + xi)*3;
    out[3*q+0] = pp[0];
    out[3*q+1] = pp[1];
    out[3*q+2] = pp[2];
}

// ======================================================================
extern "C" void kernel_launch(void* const* d_in, const int* in_sizes, int n_in,
                              void* d_out, int out_size)
{
    const float* inp   = (const float*)d_in[0];
    const float* coord = (const float*)d_in[1];
    const float* cell  = (const float*)d_in[2];
    const float* enc_w = (const float*)d_in[3];
    const float* enc_b = (const float*)d_in[4];
    const float* w1    = (const float*)d_in[5];
    const float* b1    = (const float*)d_in[6];
    const float* w2    = (const float*)d_in[7];
    const float* b2    = (const float*)d_in[8];
    const float* rw    = (const float*)d_in[9];
    const float* rb    = (const float*)d_in[10];
    const float* ow    = (const float*)d_in[11];
    const float* ob    = (const float*)d_in[12];
    const float* tw    = (const float*)d_in[13];
    const float* tb    = (const float*)d_in[14];
    const float* wc    = (const float*)d_in[15];
    const float* we    = (const float*)d_in[16];
    float* out = (float*)d_out;

    enc_kernel<<<dim3(8,8), dim3(16,16)>>>(inp, enc_w, enc_b);
    phase_kernel<<<1, dim3(64,16)>>>(w1,b1,w2,b2,rw,rb,ow,ob,wc,we);
    main_kernel<<<dim3(8,8,16), dim3(16,16)>>>();
    tail_kernel<<<dim3(16,64), dim3(32,8)>>>(tw, tb);
    query_kernel<<<NQ/256, 256>>>(coord, cell, out);
}